// round 14
// baseline (speedup 1.0000x reference)
#include <cuda_runtime.h>
#include <cooperative_groups.h>
#include <stdint.h>
#include <math.h>

namespace cg = cooperative_groups;

#define HH 96
#define WW 96
#define NPIX 9216
#define NB 32
#define NS 50
#define PPB 2304   // pixels per block; cluster of 4 covers one image

// ---------------- threefry2x32 ----------------
__device__ __forceinline__ void tf2x32(uint32_t k0, uint32_t k1,
                                       uint32_t c0, uint32_t c1,
                                       uint32_t& o0, uint32_t& o1) {
    uint32_t ks2 = k0 ^ k1 ^ 0x1BD11BDAu;
    uint32_t x0 = c0 + k0, x1 = c1 + k1;
#define TF_RND(r) { x0 += x1; x1 = (x1 << (r)) | (x1 >> (32 - (r))); x1 ^= x0; }
    TF_RND(13) TF_RND(15) TF_RND(26) TF_RND(6)   x0 += k1;  x1 += ks2 + 1u;
    TF_RND(17) TF_RND(29) TF_RND(16) TF_RND(24)  x0 += ks2; x1 += k0 + 2u;
    TF_RND(13) TF_RND(15) TF_RND(26) TF_RND(6)   x0 += k0;  x1 += k1 + 3u;
    TF_RND(17) TF_RND(29) TF_RND(16) TF_RND(24)  x0 += k1;  x1 += ks2 + 4u;
    TF_RND(13) TF_RND(15) TF_RND(26) TF_RND(6)   x0 += ks2; x1 += k0 + 5u;
#undef TF_RND
    o0 = x0; o1 = x1;
}

__device__ __forceinline__ void image_keys(int b, uint32_t& f0, uint32_t& f1,
                                           uint32_t& g0, uint32_t& g1) {
    uint32_t kb0, kb1;
    tf2x32(0u, 42u, 0u, (uint32_t)b, kb0, kb1);
    tf2x32(kb0, kb1, 0u, 0u, f0, f1);
    tf2x32(kb0, kb1, 0u, 1u, g0, g1);
}

__device__ __forceinline__ uint32_t rbits(uint32_t k0, uint32_t k1, int p) {
    uint32_t o0, o1;
    tf2x32(k0, k1, 0u, (uint32_t)p, o0, o1);
    return o0 ^ o1;
}

__device__ __forceinline__ float clip255(float x) {
    return fminf(fmaxf(x / 255.0f, 0.0f), 1.0f);
}

// ---------------- packed f32x2 helpers ----------------
__device__ __forceinline__ uint64_t pk2(float lo, float hi) {
    uint64_t r; asm("mov.b64 %0, {%1, %2};" : "=l"(r) : "f"(lo), "f"(hi)); return r;
}
__device__ __forceinline__ void unpk2(float& lo, float& hi, uint64_t v) {
    asm("mov.b64 {%0, %1}, %2;" : "=f"(lo), "=f"(hi) : "l"(v));
}
__device__ __forceinline__ uint64_t add2(uint64_t a, uint64_t b) {
    uint64_t r; asm("add.rn.f32x2 %0, %1, %2;" : "=l"(r) : "l"(a), "l"(b)); return r;
}
__device__ __forceinline__ uint64_t mul2(uint64_t a, uint64_t b) {
    uint64_t r; asm("mul.rn.f32x2 %0, %1, %2;" : "=l"(r) : "l"(a), "l"(b)); return r;
}
__device__ __forceinline__ uint64_t fma2(uint64_t a, uint64_t b, uint64_t c) {
    uint64_t r; asm("fma.rn.f32x2 %0, %1, %2, %3;" : "=l"(r) : "l"(a), "l"(b), "l"(c)); return r;
}

// ============ ONE kernel: whole pipeline, cluster of 4 = one image ============
__global__ void __launch_bounds__(1024) __cluster_dims__(4, 1, 1)
k_all(const float* __restrict__ img, float* __restrict__ out) {
    __shared__ float spix[PPB * 3];                 // 27648 B: clipped pixels
    __shared__ uint32_t lhist[512];                 // [cls][256]
    __shared__ uint32_t ghist[512];                 // rank0 merged hist
    __shared__ unsigned long long cand[1024];       // rank0 candidates; reused as lstq
    __shared__ ulonglong2 stq[150];                 // rank0: packed negated train
    __shared__ float fe[500];
    __shared__ int sel[100];
    __shared__ float msh[10];
    __shared__ float lmsh[10];
    __shared__ uint32_t bmax[3];
    __shared__ float cmx[3];
    __shared__ uint32_t keys4[4];
    __shared__ int cnts[2], pivots[2], spiv[2];

    cg::cluster_group cl = cg::this_cluster();
    int rank = blockIdx.x;                          // 0..3
    int b = blockIdx.y;
    int t = threadIdx.x, lane = t & 31, wid = t >> 5;
    int base = rank * PPB;

    if (t == 0) {
        uint32_t f0, f1, g0, g1;
        image_keys(b, f0, f1, g0, g1);
        keys4[0] = f0; keys4[1] = f1; keys4[2] = g0; keys4[3] = g1;
        cnts[0] = 0; cnts[1] = 0;
    }
    if (t < 512) lhist[t] = 0u;
    if (t < 3) bmax[t] = 0u;
    __syncthreads();

    // ---------- phase A: clip -> smem + block channel max ----------
    float m0 = 0.0f, m1 = 0.0f, m2 = 0.0f;
    #pragma unroll
    for (int k = 0; k < 3; k++) {
        if (k == 2 && t >= 256) break;
        int pi = k * 1024 + t;
        int p = base + pi;
        const float* px = img + ((size_t)b * NPIX + p) * 3;
        float c0 = clip255(px[0]);
        float c1 = clip255(px[1]);
        float c2 = clip255(px[2]);
        spix[pi * 3 + 0] = c0; spix[pi * 3 + 1] = c1; spix[pi * 3 + 2] = c2;
        m0 = fmaxf(m0, c0); m1 = fmaxf(m1, c1); m2 = fmaxf(m2, c2);
    }
    uint32_t r0 = __reduce_max_sync(0xFFFFFFFFu, __float_as_uint(m0));
    uint32_t r1 = __reduce_max_sync(0xFFFFFFFFu, __float_as_uint(m1));
    uint32_t r2 = __reduce_max_sync(0xFFFFFFFFu, __float_as_uint(m2));
    if (lane == 0) {
        atomicMax(&bmax[0], r0); atomicMax(&bmax[1], r1); atomicMax(&bmax[2], r2);
    }
    cl.sync();   // #1

    if (t < 3) {
        uint32_t mx = 0u;
        #pragma unroll
        for (int r = 0; r < 4; r++)
            mx = max(mx, cl.map_shared_rank(bmax, r)[t]);
        cmx[t] = __uint_as_float(mx);
    }
    __syncthreads();

    // ---------- phase B: validity + single threefry + local hist ----------
    float c0m = cmx[0], c1m = cmx[1], c2m = cmx[2];
    uint32_t kf0 = keys4[0], kf1 = keys4[1], kg0 = keys4[2], kg1 = keys4[3];
    uint32_t rvq[3];
    #pragma unroll
    for (int k = 0; k < 3; k++) {
        if (k == 2 && t >= 256) break;
        int pi = k * 1024 + t;
        int p = base + pi;
        float v0 = spix[pi * 3 + 0] / c0m;
        float v1 = spix[pi * 3 + 1] / c1m;
        float v2 = spix[pi * 3 + 2] / c2m;
        bool fg = (v0 > 0.0f && v0 < 0.6f) || (v1 > 0.0f && v1 < 0.6f) || (v2 > 0.0f && v2 < 0.6f);
        uint32_t bits = rbits(fg ? kf0 : kg0, fg ? kf1 : kg1, p);
        rvq[k] = ((bits >> 9) + 1u) | (fg ? 0u : (1u << 24));
        atomicAdd(&lhist[(fg ? 0 : 256) + (bits >> 24)], 1u);
    }
    __syncthreads();
    cl.sync();   // #2

    // ---------- rank0: merge hists + pivots ----------
    if (rank == 0) {
        if (t < 512) {
            uint32_t s = 0;
            #pragma unroll
            for (int r = 0; r < 4; r++)
                s += cl.map_shared_rank(lhist, r)[t];
            ghist[t] = s;
        }
        __syncthreads();
        if (wid < 2) {
            const uint32_t* sh = ghist + wid * 256;
            int csum = 0;
            #pragma unroll
            for (int i = 0; i < 8; i++) csum += (int)sh[lane * 8 + i];
            int suf = csum;
            #pragma unroll
            for (int o = 1; o < 32; o <<= 1) {
                int v = __shfl_down_sync(0xFFFFFFFFu, suf, o);
                if (lane + o < 32) suf += v;
            }
            unsigned ball = __ballot_sync(0xFFFFFFFFu, suf >= NS);
            if (ball) {
                int L = 31 - __clz(ball);
                if (lane == L) {
                    int acc = suf - csum;
                    int pv = 8 * L;
                    for (int bin = 8 * L + 7; bin >= 8 * L; bin--) {
                        acc += (int)sh[bin];
                        if (acc >= NS) { pv = bin; break; }
                    }
                    pivots[wid] = pv;
                }
            } else if (lane == 0) pivots[wid] = -1;
        }
    }
    cl.sync();   // #3

    if (t < 2) spiv[t] = cl.map_shared_rank(pivots, 0)[t];
    __syncthreads();

    // ---------- deposit candidates into rank0 smem ----------
    int pv0 = spiv[0], pv1 = spiv[1];
    int* r0cnts = cl.map_shared_rank(cnts, 0);
    unsigned long long* r0cand = cl.map_shared_rank(cand, 0);
    #pragma unroll
    for (int k = 0; k < 3; k++) {
        if (k == 2 && t >= 256) break;
        int p = base + k * 1024 + t;
        uint32_t rv = rvq[k];
        int clsv = (int)(rv >> 24);
        uint32_t v = rv & 0xFFFFFFu;
        int pvo = clsv ? pv1 : pv0;
        bool take = (pvo >= 0) ? ((int)((v - 1u) >> 15) >= pvo) : true;
        if (take) {
            int slot = atomicAdd(&r0cnts[clsv], 1);
            if (slot < 512)
                r0cand[clsv * 512 + slot] = ((unsigned long long)v << 14) |
                                            (unsigned long long)(NPIX - 1 - p);
        }
        int o = 1 - clsv;
        if (((o ? pv1 : pv0) < 0) && p < 100) {
            int slot = atomicAdd(&r0cnts[o], 1);
            if (slot < 512)
                r0cand[o * 512 + slot] = (unsigned long long)(NPIX - 1 - p);
        }
    }
    cl.sync();   // #4

    // ---------- rank0: rank + train stats + packed train ----------
    if (rank == 0) {
        {
            int cls = t >> 9, i = t & 511;
            int cnt = cnts[cls] < 512 ? cnts[cls] : 512;
            if (i < cnt) {
                unsigned long long ki = cand[cls * 512 + i];
                int rr = 0;
                for (int j = 0; j < cnt; j++) rr += (cand[cls * 512 + j] > ki);
                if (rr < NS)
                    sel[cls * NS + rr] = NPIX - 1 - (int)(ki & 0x3FFFull);
            }
        }
        __syncthreads();

        if (t < 100) {
            int p = sel[t];
            int owner = p / PPB, off = p - owner * PPB;
            const float* rsp = cl.map_shared_rank(spix, owner);
            int i = p / WW, j = p % WW;
            fe[t * 5 + 0] = rsp[off * 3 + 0] / 255.0f;
            fe[t * 5 + 1] = rsp[off * 3 + 1] / 255.0f;
            fe[t * 5 + 2] = rsp[off * 3 + 2] / 255.0f;
            fe[t * 5 + 3] = ((float)i / 96.0f) * 100.0f;
            fe[t * 5 + 4] = ((float)j / 96.0f) * 100.0f;
        }
        __syncthreads();
        if (t < 5) {
            float s = 0.0f;
            for (int r = 0; r < 100; r++) s += fe[r * 5 + t];
            float m = s / 100.0f;
            float v = 0.0f;
            for (int r = 0; r < 100; r++) { float d = fe[r * 5 + t] - m; v += d * d; }
            msh[t] = m;
            msh[5 + t] = sqrtf(v / 100.0f);
        }
        __syncthreads();
        if (t < 100) {
            int m = t >> 1, h = t & 1;
            float* dst = (float*)stq + m * 12;
            #pragma unroll
            for (int f = 0; f < 5; f++)
                dst[f * 2 + h] = -((fe[t * 5 + f] - msh[f]) / msh[5 + f]);
            dst[10 + h] = 0.0f;
        }
    }
    cl.sync();   // #5

    // ---------- phase D: copy train locally, then KNN seg ----------
    ulonglong2* lstq = (ulonglong2*)cand;   // cand is dead; reuse its 8KB
    {
        const float4* src = (const float4*)cl.map_shared_rank(stq, 0);
        if (t < 150) ((float4*)lstq)[t] = src[t];
        const float* msrc = cl.map_shared_rank(msh, 0);
        if (t < 10) lmsh[t] = msrc[t];
    }
    __syncthreads();

    float mm0 = lmsh[0], mm1 = lmsh[1], mm2 = lmsh[2], mm3 = lmsh[3], mm4 = lmsh[4];
    float ss0 = lmsh[5], ss1 = lmsh[6], ss2 = lmsh[7], ss3 = lmsh[8], ss4 = lmsh[9];
    const float INF = __int_as_float(0x7F800000);

    // --- main pass: pixels (t, t+1024) interleaved, full neighbor set ---
    {
        int piA = t, piB = t + 1024;
        int pA = base + piA, pB = base + piB;
        float cAx = spix[piA * 3 + 0], cAy = spix[piA * 3 + 1], cAz = spix[piA * 3 + 2];
        float cBx = spix[piB * 3 + 0], cBy = spix[piB * 3 + 1], cBz = spix[piB * 3 + 2];

        uint64_t tpA[5], tpB[5];
        {
            int i = pA / WW, j = pA % WW;
            float v;
            v = (cAx / 255.0f - mm0) / ss0; tpA[0] = pk2(v, v);
            v = (cAy / 255.0f - mm1) / ss1; tpA[1] = pk2(v, v);
            v = (cAz / 255.0f - mm2) / ss2; tpA[2] = pk2(v, v);
            v = (((float)i / 96.0f) * 100.0f - mm3) / ss3; tpA[3] = pk2(v, v);
            v = (((float)j / 96.0f) * 100.0f - mm4) / ss4; tpA[4] = pk2(v, v);
        }
        {
            int i = pB / WW, j = pB % WW;
            float v;
            v = (cBx / 255.0f - mm0) / ss0; tpB[0] = pk2(v, v);
            v = (cBy / 255.0f - mm1) / ss1; tpB[1] = pk2(v, v);
            v = (cBz / 255.0f - mm2) / ss2; tpB[2] = pk2(v, v);
            v = (((float)i / 96.0f) * 100.0f - mm3) / ss3; tpB[3] = pk2(v, v);
            v = (((float)j / 96.0f) * 100.0f - mm4) / ss4; tpB[4] = pk2(v, v);
        }

        float a1A = INF, a2A = INF, a1B = INF, a2B = INF;
        #pragma unroll 5
        for (int m = 0; m < 25; m++) {
            ulonglong2 q0 = lstq[3 * m], q1 = lstq[3 * m + 1], q2 = lstq[3 * m + 2];
            {
                uint64_t d0 = add2(tpA[0], q0.x), d1 = add2(tpA[1], q0.y);
                uint64_t d2_ = add2(tpA[2], q1.x), d3 = add2(tpA[3], q1.y);
                uint64_t d4 = add2(tpA[4], q2.x);
                uint64_t s = mul2(d0, d0);
                s = fma2(d1, d1, s); s = fma2(d2_, d2_, s);
                s = fma2(d3, d3, s); s = fma2(d4, d4, s);
                float lo, hi; unpk2(lo, hi, s);
                float u = fmaxf(lo, a1A); a2A = fminf(u, a2A); a1A = fminf(lo, a1A);
                u = fmaxf(hi, a1A);       a2A = fminf(u, a2A); a1A = fminf(hi, a1A);
            }
            {
                uint64_t d0 = add2(tpB[0], q0.x), d1 = add2(tpB[1], q0.y);
                uint64_t d2_ = add2(tpB[2], q1.x), d3 = add2(tpB[3], q1.y);
                uint64_t d4 = add2(tpB[4], q2.x);
                uint64_t s = mul2(d0, d0);
                s = fma2(d1, d1, s); s = fma2(d2_, d2_, s);
                s = fma2(d3, d3, s); s = fma2(d4, d4, s);
                float lo, hi; unpk2(lo, hi, s);
                float u = fmaxf(lo, a1B); a2B = fminf(u, a2B); a1B = fminf(lo, a1B);
                u = fmaxf(hi, a1B);       a2B = fminf(u, a2B); a1B = fminf(hi, a1B);
            }
        }

        float saA = sqrtf(a2A), saB = sqrtf(a2B);
        uint32_t xa = __float_as_uint(a2A);
        while (xa > 0u && sqrtf(__uint_as_float(xa - 1u)) >= saA) xa--;
        float thA = __uint_as_float(xa);
        uint32_t xb = __float_as_uint(a2B);
        while (xb > 0u && sqrtf(__uint_as_float(xb - 1u)) >= saB) xb--;
        float thB = __uint_as_float(xb);

        int cntA = 0, cntB = 0;
        #pragma unroll 5
        for (int m = 25; m < 50; m++) {
            ulonglong2 q0 = lstq[3 * m], q1 = lstq[3 * m + 1], q2 = lstq[3 * m + 2];
            {
                uint64_t d0 = add2(tpA[0], q0.x), d1 = add2(tpA[1], q0.y);
                uint64_t d2_ = add2(tpA[2], q1.x), d3 = add2(tpA[3], q1.y);
                uint64_t d4 = add2(tpA[4], q2.x);
                uint64_t s = mul2(d0, d0);
                s = fma2(d1, d1, s); s = fma2(d2_, d2_, s);
                s = fma2(d3, d3, s); s = fma2(d4, d4, s);
                float lo, hi; unpk2(lo, hi, s);
                cntA += (lo < thA);
                cntA += (hi < thA);
            }
            {
                uint64_t d0 = add2(tpB[0], q0.x), d1 = add2(tpB[1], q0.y);
                uint64_t d2_ = add2(tpB[2], q1.x), d3 = add2(tpB[3], q1.y);
                uint64_t d4 = add2(tpB[4], q2.x);
                uint64_t s = mul2(d0, d0);
                s = fma2(d1, d1, s); s = fma2(d2_, d2_, s);
                s = fma2(d3, d3, s); s = fma2(d4, d4, s);
                float lo, hi; unpk2(lo, hi, s);
                cntB += (lo < thB);
                cntB += (hi < thB);
            }
        }

        float* oA = out + ((size_t)b * NPIX + pA) * 3;
        if (cntA < 4) { oA[0] = cAx; oA[1] = cAy; oA[2] = cAz; }
        else          { oA[0] = 0.0f; oA[1] = 0.0f; oA[2] = 0.0f; }
        float* oB = out + ((size_t)b * NPIX + pB) * 3;
        if (cntB < 4) { oB[0] = cBx; oB[1] = cBy; oB[2] = cBz; }
        else          { oB[0] = 0.0f; oB[1] = 0.0f; oB[2] = 0.0f; }
    }

    // --- balanced epilogue: 256 px, one pixel per 4-lane quad ---
    {
        int pi = 2048 + (t >> 2);
        int sub = t & 3;
        int p = base + pi;
        float cx = spix[pi * 3 + 0], cy = spix[pi * 3 + 1], cz = spix[pi * 3 + 2];
        uint64_t tp[5];
        {
            int i = p / WW, j = p % WW;
            float v;
            v = (cx / 255.0f - mm0) / ss0; tp[0] = pk2(v, v);
            v = (cy / 255.0f - mm1) / ss1; tp[1] = pk2(v, v);
            v = (cz / 255.0f - mm2) / ss2; tp[2] = pk2(v, v);
            v = (((float)i / 96.0f) * 100.0f - mm3) / ss3; tp[3] = pk2(v, v);
            v = (((float)j / 96.0f) * 100.0f - mm4) / ss4; tp[4] = pk2(v, v);
        }
        // partial 2-smallest fg over pairs m ≡ sub (mod 4)
        float a1 = INF, a2 = INF;
        for (int m = sub; m < 25; m += 4) {
            ulonglong2 q0 = lstq[3 * m], q1 = lstq[3 * m + 1], q2 = lstq[3 * m + 2];
            uint64_t d0 = add2(tp[0], q0.x), d1 = add2(tp[1], q0.y);
            uint64_t d2_ = add2(tp[2], q1.x), d3 = add2(tp[3], q1.y);
            uint64_t d4 = add2(tp[4], q2.x);
            uint64_t s = mul2(d0, d0);
            s = fma2(d1, d1, s); s = fma2(d2_, d2_, s);
            s = fma2(d3, d3, s); s = fma2(d4, d4, s);
            float lo, hi; unpk2(lo, hi, s);
            float u = fmaxf(lo, a1); a2 = fminf(u, a2); a1 = fminf(lo, a1);
            u = fmaxf(hi, a1);       a2 = fminf(u, a2); a1 = fminf(hi, a1);
        }
        // merge sorted pairs across the quad (exact value-multiset merge)
        #pragma unroll
        for (int o = 1; o <= 2; o <<= 1) {
            float b1 = __shfl_xor_sync(0xFFFFFFFFu, a1, o);
            float b2 = __shfl_xor_sync(0xFFFFFFFFu, a2, o);
            float n1 = fminf(a1, b1);
            float n2 = fminf(fmaxf(a1, b1), fminf(a2, b2));
            a1 = n1; a2 = n2;
        }
        // threshold (same value on all 4 lanes)
        float sa = sqrtf(a2);
        uint32_t xu = __float_as_uint(a2);
        while (xu > 0u && sqrtf(__uint_as_float(xu - 1u)) >= sa) xu--;
        float th = __uint_as_float(xu);

        int cnt = 0;
        for (int m = 25 + sub; m < 50; m += 4) {
            ulonglong2 q0 = lstq[3 * m], q1 = lstq[3 * m + 1], q2 = lstq[3 * m + 2];
            uint64_t d0 = add2(tp[0], q0.x), d1 = add2(tp[1], q0.y);
            uint64_t d2_ = add2(tp[2], q1.x), d3 = add2(tp[3], q1.y);
            uint64_t d4 = add2(tp[4], q2.x);
            uint64_t s = mul2(d0, d0);
            s = fma2(d1, d1, s); s = fma2(d2_, d2_, s);
            s = fma2(d3, d3, s); s = fma2(d4, d4, s);
            float lo, hi; unpk2(lo, hi, s);
            cnt += (lo < th);
            cnt += (hi < th);
        }
        cnt += __shfl_xor_sync(0xFFFFFFFFu, cnt, 1);
        cnt += __shfl_xor_sync(0xFFFFFFFFu, cnt, 2);

        if (sub == 0) {
            float* o = out + ((size_t)b * NPIX + p) * 3;
            if (cnt < 4) { o[0] = cx; o[1] = cy; o[2] = cz; }
            else         { o[0] = 0.0f; o[1] = 0.0f; o[2] = 0.0f; }
        }
    }
}

// ---------------- launch ----------------
extern "C" void kernel_launch(void* const* d_in, const int* in_sizes, int n_in,
                              void* d_out, int out_size) {
    const float* img = (const float*)d_in[0];
    float* out = (float*)d_out;
    k_all<<<dim3(4, NB), 1024>>>(img, out);
}

// round 16
// speedup vs baseline: 1.0674x; 1.0674x over previous
#include <cuda_runtime.h>
#include <cooperative_groups.h>
#include <stdint.h>
#include <math.h>

namespace cg = cooperative_groups;

#define HH 96
#define WW 96
#define NPIX 9216
#define NB 32
#define NS 50
#define PPB 2304   // pixels per block (cluster of 4 covers one image)

// ---------------- scratch ----------------
__device__ float    g_trp[NB * 600];          // negated standardized, pair-packed
__device__ float    g_ms[NB * 10];            // mean[5], std[5]
__device__ float4   g_clip4[NB * NPIX];       // img_p (clipped) per pixel

// ---------------- threefry2x32 ----------------
__device__ __forceinline__ void tf2x32(uint32_t k0, uint32_t k1,
                                       uint32_t c0, uint32_t c1,
                                       uint32_t& o0, uint32_t& o1) {
    uint32_t ks2 = k0 ^ k1 ^ 0x1BD11BDAu;
    uint32_t x0 = c0 + k0, x1 = c1 + k1;
#define TF_RND(r) { x0 += x1; x1 = (x1 << (r)) | (x1 >> (32 - (r))); x1 ^= x0; }
    TF_RND(13) TF_RND(15) TF_RND(26) TF_RND(6)   x0 += k1;  x1 += ks2 + 1u;
    TF_RND(17) TF_RND(29) TF_RND(16) TF_RND(24)  x0 += ks2; x1 += k0 + 2u;
    TF_RND(13) TF_RND(15) TF_RND(26) TF_RND(6)   x0 += k0;  x1 += k1 + 3u;
    TF_RND(17) TF_RND(29) TF_RND(16) TF_RND(24)  x0 += k1;  x1 += ks2 + 4u;
    TF_RND(13) TF_RND(15) TF_RND(26) TF_RND(6)   x0 += ks2; x1 += k0 + 5u;
#undef TF_RND
    o0 = x0; o1 = x1;
}

__device__ __forceinline__ void image_keys(int b, uint32_t& f0, uint32_t& f1,
                                           uint32_t& g0, uint32_t& g1) {
    uint32_t kb0, kb1;
    tf2x32(0u, 42u, 0u, (uint32_t)b, kb0, kb1);
    tf2x32(kb0, kb1, 0u, 0u, f0, f1);
    tf2x32(kb0, kb1, 0u, 1u, g0, g1);
}

__device__ __forceinline__ uint32_t rbits(uint32_t k0, uint32_t k1, int p) {
    uint32_t o0, o1;
    tf2x32(k0, k1, 0u, (uint32_t)p, o0, o1);
    return o0 ^ o1;
}

__device__ __forceinline__ float clip255(float x) {
    return fminf(fmaxf(x / 255.0f, 0.0f), 1.0f);
}

// ---------------- packed f32x2 helpers ----------------
__device__ __forceinline__ uint64_t pk2(float lo, float hi) {
    uint64_t r; asm("mov.b64 %0, {%1, %2};" : "=l"(r) : "f"(lo), "f"(hi)); return r;
}
__device__ __forceinline__ void unpk2(float& lo, float& hi, uint64_t v) {
    asm("mov.b64 {%0, %1}, %2;" : "=f"(lo), "=f"(hi) : "l"(v));
}
__device__ __forceinline__ uint64_t add2(uint64_t a, uint64_t b) {
    uint64_t r; asm("add.rn.f32x2 %0, %1, %2;" : "=l"(r) : "l"(a), "l"(b)); return r;
}
__device__ __forceinline__ uint64_t mul2(uint64_t a, uint64_t b) {
    uint64_t r; asm("mul.rn.f32x2 %0, %1, %2;" : "=l"(r) : "l"(a), "l"(b)); return r;
}
__device__ __forceinline__ uint64_t fma2(uint64_t a, uint64_t b, uint64_t c) {
    uint64_t r; asm("fma.rn.f32x2 %0, %1, %2, %3;" : "=l"(r) : "l"(a), "l"(b), "l"(c)); return r;
}

// ============ K1: fused clip+cmax+validity+pick+rank+train (cluster=image) ============
__global__ void __launch_bounds__(1024) __cluster_dims__(4, 1, 1)
k_fused(const float* __restrict__ img) {
    __shared__ uint32_t lhist[512];                 // this block's [cls][256]
    __shared__ uint32_t bmax[3];                    // this block's channel max
    __shared__ uint32_t ghist[512];                 // rank0: merged hist
    __shared__ unsigned long long cand[2 * 512];    // rank0: candidates
    __shared__ int cnts[2];                         // rank0
    __shared__ int pivots[2];                       // rank0
    __shared__ int spiv[2];
    __shared__ float cmx[3];
    __shared__ uint32_t keys4[4];
    __shared__ float fe[500];
    __shared__ int sel[100];
    __shared__ float msh[10];

    cg::cluster_group cl = cg::this_cluster();
    int rank = blockIdx.x;                          // 0..3 within cluster
    int b = blockIdx.y;
    int t = threadIdx.x, lane = t & 31, wid = t >> 5;
    int base = rank * PPB;

    if (t == 0) {
        uint32_t f0, f1, g0, g1;
        image_keys(b, f0, f1, g0, g1);
        keys4[0] = f0; keys4[1] = f1; keys4[2] = g0; keys4[3] = g1;
        cnts[0] = 0; cnts[1] = 0;
    }
    if (t < 512) { lhist[t] = 0u; ghist[t] = 0u; }
    if (t < 3) bmax[t] = 0u;
    __syncthreads();

    // ---------- phase A: clip + store + block channel max ----------
    float4 cpx[3];
    float m0 = 0.0f, m1 = 0.0f, m2 = 0.0f;
    #pragma unroll
    for (int k = 0; k < 3; k++) {
        if (k == 2 && t >= 256) break;
        int p = base + k * 1024 + t;
        const float* px = img + ((size_t)b * NPIX + p) * 3;
        float c0 = clip255(px[0]);
        float c1 = clip255(px[1]);
        float c2 = clip255(px[2]);
        cpx[k] = make_float4(c0, c1, c2, 0.0f);
        g_clip4[(size_t)b * NPIX + p] = cpx[k];
        m0 = fmaxf(m0, c0); m1 = fmaxf(m1, c1); m2 = fmaxf(m2, c2);
    }
    uint32_t r0 = __reduce_max_sync(0xFFFFFFFFu, __float_as_uint(m0));
    uint32_t r1 = __reduce_max_sync(0xFFFFFFFFu, __float_as_uint(m1));
    uint32_t r2 = __reduce_max_sync(0xFFFFFFFFu, __float_as_uint(m2));
    if (lane == 0) {
        atomicMax(&bmax[0], r0); atomicMax(&bmax[1], r1); atomicMax(&bmax[2], r2);
    }
    cl.sync();   // #1: all blocks' bmax ready

    // cluster max = max over 4 ranks' bmax (DSMEM reads)
    if (t < 3) {
        uint32_t mx = 0u;
        #pragma unroll
        for (int r = 0; r < 4; r++) {
            const uint32_t* rb = cl.map_shared_rank(bmax, r);
            mx = max(mx, rb[t]);
        }
        cmx[t] = __uint_as_float(mx);
    }
    __syncthreads();

    // ---------- phase B: validity + single threefry + local hist ----------
    float c0m = cmx[0], c1m = cmx[1], c2m = cmx[2];
    uint32_t kf0 = keys4[0], kf1 = keys4[1], kg0 = keys4[2], kg1 = keys4[3];
    uint32_t rvq[3];
    #pragma unroll
    for (int k = 0; k < 3; k++) {
        if (k == 2 && t >= 256) break;
        int p = base + k * 1024 + t;
        float4 c = cpx[k];
        float v0 = c.x / c0m;
        float v1 = c.y / c1m;
        float v2 = c.z / c2m;
        bool fg = (v0 > 0.0f && v0 < 0.6f) || (v1 > 0.0f && v1 < 0.6f) || (v2 > 0.0f && v2 < 0.6f);
        uint32_t bits = rbits(fg ? kf0 : kg0, fg ? kf1 : kg1, p);
        rvq[k] = ((bits >> 9) + 1u) | (fg ? 0u : (1u << 24));
        atomicAdd(&lhist[(fg ? 0 : 256) + (bits >> 24)], 1u);
    }
    __syncthreads();
    cl.sync();   // #2: all blocks' lhist complete

    // ---------- rank0: merge hists + pivots ----------
    if (rank == 0) {
        if (t < 512) {
            uint32_t s = 0;
            #pragma unroll
            for (int r = 0; r < 4; r++)
                s += cl.map_shared_rank(lhist, r)[t];
            ghist[t] = s;
        }
        __syncthreads();
        if (wid < 2) {
            const uint32_t* sh = ghist + wid * 256;
            int csum = 0;
            #pragma unroll
            for (int i = 0; i < 8; i++) csum += (int)sh[lane * 8 + i];
            int suf = csum;
            #pragma unroll
            for (int o = 1; o < 32; o <<= 1) {
                int v = __shfl_down_sync(0xFFFFFFFFu, suf, o);
                if (lane + o < 32) suf += v;
            }
            unsigned ball = __ballot_sync(0xFFFFFFFFu, suf >= NS);
            if (ball) {
                int L = 31 - __clz(ball);
                if (lane == L) {
                    int acc = suf - csum;
                    int pv = 8 * L;
                    for (int bin = 8 * L + 7; bin >= 8 * L; bin--) {
                        acc += (int)sh[bin];
                        if (acc >= NS) { pv = bin; break; }
                    }
                    pivots[wid] = pv;
                }
            } else if (lane == 0) pivots[wid] = -1;
        }
    }
    cl.sync();   // #3: pivots ready

    if (t < 2) spiv[t] = cl.map_shared_rank(pivots, 0)[t];
    __syncthreads();

    // ---------- deposit candidates into rank0 smem ----------
    int pv0 = spiv[0], pv1 = spiv[1];
    int* r0cnts = cl.map_shared_rank(cnts, 0);
    unsigned long long* r0cand = cl.map_shared_rank(cand, 0);
    #pragma unroll
    for (int k = 0; k < 3; k++) {
        if (k == 2 && t >= 256) break;
        int p = base + k * 1024 + t;
        uint32_t rv = rvq[k];
        int clsv = (int)(rv >> 24);
        uint32_t v = rv & 0xFFFFFFu;
        int pvo = clsv ? pv1 : pv0;
        bool take = (pvo >= 0) ? ((int)((v - 1u) >> 15) >= pvo) : true;
        if (take) {
            int slot = atomicAdd(&r0cnts[clsv], 1);
            if (slot < 512)
                r0cand[clsv * 512 + slot] = ((unsigned long long)v << 14) |
                                            (unsigned long long)(NPIX - 1 - p);
        }
        int o = 1 - clsv;
        if (((o ? pv1 : pv0) < 0) && p < 100) {
            int slot = atomicAdd(&r0cnts[o], 1);
            if (slot < 512)
                r0cand[o * 512 + slot] = (unsigned long long)(NPIX - 1 - p);
        }
    }
    cl.sync();   // #4: deposits visible to rank0

    // ---------- rank0: rank + train (others exit) ----------
    if (rank == 0) {
        {
            int cls = t >> 9, i = t & 511;
            int cnt = cnts[cls] < 512 ? cnts[cls] : 512;
            if (i < cnt) {
                unsigned long long ki = cand[cls * 512 + i];
                int rr = 0;
                for (int j = 0; j < cnt; j++) rr += (cand[cls * 512 + j] > ki);
                if (rr < NS)
                    sel[cls * NS + rr] = NPIX - 1 - (int)(ki & 0x3FFFull);
            }
        }
        __syncthreads();

        if (t < 100) {
            int p = sel[t];
            int i = p / WW, j = p % WW;
            float4 c = g_clip4[(size_t)b * NPIX + p];
            fe[t * 5 + 0] = c.x / 255.0f;
            fe[t * 5 + 1] = c.y / 255.0f;
            fe[t * 5 + 2] = c.z / 255.0f;
            fe[t * 5 + 3] = ((float)i / 96.0f) * 100.0f;
            fe[t * 5 + 4] = ((float)j / 96.0f) * 100.0f;
        }
        __syncthreads();
        if (t < 5) {
            float s = 0.0f;
            for (int r = 0; r < 100; r++) s += fe[r * 5 + t];
            float m = s / 100.0f;
            float v = 0.0f;
            for (int r = 0; r < 100; r++) { float d = fe[r * 5 + t] - m; v += d * d; }
            msh[t] = m;
            msh[5 + t] = sqrtf(v / 100.0f);
        }
        __syncthreads();
        if (t < 100) {
            int m = t >> 1, h = t & 1;
            float* dst = g_trp + ((size_t)b * 50 + m) * 12;
            #pragma unroll
            for (int f = 0; f < 5; f++)
                dst[f * 2 + h] = -((fe[t * 5 + f] - msh[f]) / msh[5 + f]);
            dst[5 * 2 + h] = 0.0f;
        }
        if (t < 10) g_ms[b * 10 + t] = msh[t];
    }
}

// ============ K2: KNN segmentation, 2 pixels/thread, 256-thread blocks ============
__global__ void __launch_bounds__(256) k_seg(float* __restrict__ out) {
    __shared__ ulonglong2 stq[150];  // 50 pairs x 3 ulonglong2 = 600 floats
    __shared__ float ms[10];
    int b = blockIdx.y, t = threadIdx.x;

    if (t < 150) ((float4*)stq)[t] = ((const float4*)(g_trp + (size_t)b * 600))[t];
    if (t < 10) ms[t] = g_ms[b * 10 + t];
    __syncthreads();

    float m0 = ms[0], m1 = ms[1], m2 = ms[2], m3 = ms[3], m4 = ms[4];
    float s0 = ms[5], s1 = ms[6], s2 = ms[7], s3 = ms[8], s4 = ms[9];

    int p0 = blockIdx.x * 512 + t;        // pixels p0 and p0+256
    float4 cA = g_clip4[(size_t)b * NPIX + p0];
    float4 cB = g_clip4[(size_t)b * NPIX + p0 + 256];

    uint64_t tpA[5], tpB[5];
    {
        int i = p0 / WW, j = p0 % WW;
        float v;
        v = (cA.x / 255.0f - m0) / s0; tpA[0] = pk2(v, v);
        v = (cA.y / 255.0f - m1) / s1; tpA[1] = pk2(v, v);
        v = (cA.z / 255.0f - m2) / s2; tpA[2] = pk2(v, v);
        v = (((float)i / 96.0f) * 100.0f - m3) / s3; tpA[3] = pk2(v, v);
        v = (((float)j / 96.0f) * 100.0f - m4) / s4; tpA[4] = pk2(v, v);
    }
    {
        int p1 = p0 + 256;
        int i = p1 / WW, j = p1 % WW;
        float v;
        v = (cB.x / 255.0f - m0) / s0; tpB[0] = pk2(v, v);
        v = (cB.y / 255.0f - m1) / s1; tpB[1] = pk2(v, v);
        v = (cB.z / 255.0f - m2) / s2; tpB[2] = pk2(v, v);
        v = (((float)i / 96.0f) * 100.0f - m3) / s3; tpB[3] = pk2(v, v);
        v = (((float)j / 96.0f) * 100.0f - m4) / s4; tpB[4] = pk2(v, v);
    }

    const float INF = __int_as_float(0x7F800000);
    float a1A = INF, a2A = INF, a1B = INF, a2B = INF;

    #pragma unroll 5
    for (int m = 0; m < 25; m++) {                  // fg pairs, both pixels
        ulonglong2 q0 = stq[3 * m], q1 = stq[3 * m + 1], q2 = stq[3 * m + 2];
        {
            uint64_t d0 = add2(tpA[0], q0.x), d1 = add2(tpA[1], q0.y);
            uint64_t d2_ = add2(tpA[2], q1.x), d3 = add2(tpA[3], q1.y);
            uint64_t d4 = add2(tpA[4], q2.x);
            uint64_t s = mul2(d0, d0);
            s = fma2(d1, d1, s); s = fma2(d2_, d2_, s);
            s = fma2(d3, d3, s); s = fma2(d4, d4, s);
            float lo, hi; unpk2(lo, hi, s);
            float u = fmaxf(lo, a1A); a2A = fminf(u, a2A); a1A = fminf(lo, a1A);
            u = fmaxf(hi, a1A);       a2A = fminf(u, a2A); a1A = fminf(hi, a1A);
        }
        {
            uint64_t d0 = add2(tpB[0], q0.x), d1 = add2(tpB[1], q0.y);
            uint64_t d2_ = add2(tpB[2], q1.x), d3 = add2(tpB[3], q1.y);
            uint64_t d4 = add2(tpB[4], q2.x);
            uint64_t s = mul2(d0, d0);
            s = fma2(d1, d1, s); s = fma2(d2_, d2_, s);
            s = fma2(d3, d3, s); s = fma2(d4, d4, s);
            float lo, hi; unpk2(lo, hi, s);
            float u = fmaxf(lo, a1B); a2B = fminf(u, a2B); a1B = fminf(lo, a1B);
            u = fmaxf(hi, a1B);       a2B = fminf(u, a2B); a1B = fminf(hi, a1B);
        }
    }

    // threshold: smallest float x with sqrtf(x) >= sqrtf(a2) (exact ulp walk)
    float saA = sqrtf(a2A), saB = sqrtf(a2B);
    uint32_t xa = __float_as_uint(a2A);
    while (xa > 0u && sqrtf(__uint_as_float(xa - 1u)) >= saA) xa--;
    float thA = __uint_as_float(xa);
    uint32_t xb = __float_as_uint(a2B);
    while (xb > 0u && sqrtf(__uint_as_float(xb - 1u)) >= saB) xb--;
    float thB = __uint_as_float(xb);

    int cntA = 0, cntB = 0;
    #pragma unroll 5
    for (int m = 25; m < 50; m++) {                 // bg pairs, both pixels
        ulonglong2 q0 = stq[3 * m], q1 = stq[3 * m + 1], q2 = stq[3 * m + 2];
        {
            uint64_t d0 = add2(tpA[0], q0.x), d1 = add2(tpA[1], q0.y);
            uint64_t d2_ = add2(tpA[2], q1.x), d3 = add2(tpA[3], q1.y);
            uint64_t d4 = add2(tpA[4], q2.x);
            uint64_t s = mul2(d0, d0);
            s = fma2(d1, d1, s); s = fma2(d2_, d2_, s);
            s = fma2(d3, d3, s); s = fma2(d4, d4, s);
            float lo, hi; unpk2(lo, hi, s);
            cntA += (lo < thA);
            cntA += (hi < thA);
        }
        {
            uint64_t d0 = add2(tpB[0], q0.x), d1 = add2(tpB[1], q0.y);
            uint64_t d2_ = add2(tpB[2], q1.x), d3 = add2(tpB[3], q1.y);
            uint64_t d4 = add2(tpB[4], q2.x);
            uint64_t s = mul2(d0, d0);
            s = fma2(d1, d1, s); s = fma2(d2_, d2_, s);
            s = fma2(d3, d3, s); s = fma2(d4, d4, s);
            float lo, hi; unpk2(lo, hi, s);
            cntB += (lo < thB);
            cntB += (hi < thB);
        }
    }

    // seg = 1 iff fewer than 4 bg sqrt-distances strictly below sqrtf(a2)
    float* oA = out + ((size_t)b * NPIX + p0) * 3;
    if (cntA < 4) { oA[0] = cA.x; oA[1] = cA.y; oA[2] = cA.z; }
    else          { oA[0] = 0.0f; oA[1] = 0.0f; oA[2] = 0.0f; }
    float* oB = out + ((size_t)b * NPIX + p0 + 256) * 3;
    if (cntB < 4) { oB[0] = cB.x; oB[1] = cB.y; oB[2] = cB.z; }
    else          { oB[0] = 0.0f; oB[1] = 0.0f; oB[2] = 0.0f; }
}

// ---------------- launch ----------------
extern "C" void kernel_launch(void* const* d_in, const int* in_sizes, int n_in,
                              void* d_out, int out_size) {
    const float* img = (const float*)d_in[0];
    float* out = (float*)d_out;
    k_fused<<<dim3(4, NB), 1024>>>(img);
    k_seg<<<dim3(18, NB), 256>>>(out);
}